// round 1
// baseline (speedup 1.0000x reference)
#include <cuda_runtime.h>
#include <math_constants.h>

// Problem constants
#define B_      4
#define C_      64      // C_IN == C_OUT
#define H_      128
#define W_      128
#define LOC_    2
#define K_      5
#define KK_     25      // K*K
#define CKK_    1600    // C_IN * K * K
#define PIX_    (H_ * W_)            // 16384 pixels per plane
#define PLANE_  (B_ * C_ * PIX_)     // 4,194,304 elements per output tensor
#define SPIX_   (B_ * PIX_)          // 65536: (b,h,w) grid

// Scratch (allocation-free: __device__ globals)
__device__ float g_s[SPIX_];         // channel sum
__device__ float g_denom[SPIX_];     // max(5x5 box sum, 5)
__device__ int   g_nnz[C_];
__device__ float g_wsum[C_];
__device__ int   g_spk[C_ * CKK_];   // sparse column indices per output row
__device__ float g_spw[C_ * CKK_];   // sparse weights per output row

// ---------------------------------------------------------------------------
// Kernel 1: sparsify W_lateral + row sums. 1 block, 64 threads (one per o).
// ---------------------------------------------------------------------------
__global__ void k_prep(const float* __restrict__ Wl) {
    int o = threadIdx.x;
    if (o >= C_) return;
    const float* row = Wl + (size_t)o * CKK_;
    int cnt = 0;
    float s = 0.0f;
    for (int k = 0; k < CKK_; ++k) {
        float v = row[k];
        s += v;
        if (v != 0.0f) {
            g_spk[o * CKK_ + cnt] = k;
            g_spw[o * CKK_ + cnt] = v;
            ++cnt;
        }
    }
    g_nnz[o] = cnt;
    g_wsum[o] = s;
}

// ---------------------------------------------------------------------------
// Kernel 2: channel sum  s[b,h,w] = sum_c x[b,c,h,w]
// ---------------------------------------------------------------------------
__global__ void k_chansum(const float* __restrict__ x) {
    int idx = blockIdx.x * blockDim.x + threadIdx.x;   // 0..SPIX_-1
    if (idx >= SPIX_) return;
    int b = idx >> 14;          // /16384
    int p = idx & (PIX_ - 1);
    const float* base = x + (size_t)b * C_ * PIX_ + p;
    float s = 0.0f;
#pragma unroll 8
    for (int c = 0; c < C_; ++c) s += base[(size_t)c * PIX_];
    g_s[idx] = s;
}

// ---------------------------------------------------------------------------
// Kernel 3: 5x5 zero-padded box sum of s, clamped at min_support=5
// ---------------------------------------------------------------------------
__global__ void k_box(void) {
    int idx = blockIdx.x * blockDim.x + threadIdx.x;
    if (idx >= SPIX_) return;
    int b = idx >> 14;
    int p = idx & (PIX_ - 1);
    int h = p >> 7;
    int w = p & (W_ - 1);
    const float* sp = g_s + b * PIX_;
    float acc = 0.0f;
#pragma unroll
    for (int dj = -LOC_; dj <= LOC_; ++dj) {
        int hs = h + dj;
        if (hs < 0 || hs >= H_) continue;
#pragma unroll
        for (int dk = -LOC_; dk <= LOC_; ++dk) {
            int ws = w + dk;
            if (ws < 0 || ws >= W_) continue;
            acc += sp[hs * W_ + ws];
        }
    }
    g_denom[idx] = fmaxf(acc, (float)K_);
}

// ---------------------------------------------------------------------------
// Kernel 4: one block per (b,o) plane.
//   pass 1: sparse-gather x_lateral, write; t = xl/denom/(1e-10+wsum) -> smem
//   block max-reduce; pass 2: xn = t/(1e-10+max), bin = (xn^3 >= 0.5)
// Dynamic smem layout: [ t: PIX_ floats | sk: CKK_ ints | sw: CKK_ floats ]
// ---------------------------------------------------------------------------
__global__ void k_main(const float* __restrict__ x, float* __restrict__ out) {
    extern __shared__ float sm[];
    float* t  = sm;                          // 16384 floats
    int*   sk = (int*)(sm + PIX_);           // 1600 ints
    float* sw = (float*)(sk + CKK_);         // 1600 floats
    __shared__ float red[32];
    __shared__ float s_bmax;

    const int bo = blockIdx.x;               // 0..255
    const int b  = bo >> 6;
    const int o  = bo & (C_ - 1);
    const int tid = threadIdx.x;
    const int NT = blockDim.x;               // 256

    const int nnz = g_nnz[o];
    for (int e = tid; e < nnz; e += NT) {
        sk[e] = g_spk[o * CKK_ + e];
        sw[e] = g_spw[o * CKK_ + e];
    }
    __syncthreads();

    const float invw = 1.0f / (1e-10f + g_wsum[o]);
    const float* xb     = x + (size_t)b * C_ * PIX_;
    const float* denomb = g_denom + b * PIX_;
    float* out_xl  = out + (size_t)bo * PIX_;
    float* out_xn  = out + (size_t)PLANE_     + (size_t)bo * PIX_;
    float* out_bin = out + (size_t)2 * PLANE_ + (size_t)bo * PIX_;

    float lmax = -CUDART_INF_F;
    for (int p = tid; p < PIX_; p += NT) {
        int h = p >> 7;
        int w = p & (W_ - 1);
        float acc = 0.0f;
        for (int e = 0; e < nnz; ++e) {
            int k = sk[e];
            int c  = k / KK_;
            int r  = k - c * KK_;
            int j  = r / K_;
            int kk = r - j * K_;
            int hs = h + j - LOC_;
            int ws = w + kk - LOC_;
            if (hs >= 0 && hs < H_ && ws >= 0 && ws < W_)
                acc += sw[e] * xb[(size_t)c * PIX_ + hs * W_ + ws];
        }
        out_xl[p] = acc;
        float tv = (acc / denomb[p]) * invw;
        t[p] = tv;
        lmax = fmaxf(lmax, tv);
    }

    // block max reduction
#pragma unroll
    for (int off = 16; off > 0; off >>= 1)
        lmax = fmaxf(lmax, __shfl_xor_sync(0xFFFFFFFFu, lmax, off));
    if ((tid & 31) == 0) red[tid >> 5] = lmax;
    __syncthreads();
    if (tid < 32) {
        float v = (tid < (NT >> 5)) ? red[tid] : -CUDART_INF_F;
#pragma unroll
        for (int off = 16; off > 0; off >>= 1)
            v = fmaxf(v, __shfl_xor_sync(0xFFFFFFFFu, v, off));
        if (tid == 0) s_bmax = v;
    }
    __syncthreads();

    const float invm = 1.0f / (1e-10f + s_bmax);
    for (int p = tid; p < PIX_; p += NT) {
        float xn = t[p] * invm;
        out_xn[p]  = xn;
        out_bin[p] = (xn * xn * xn >= 0.5f) ? 1.0f : 0.0f;
    }
}

// ---------------------------------------------------------------------------
extern "C" void kernel_launch(void* const* d_in, const int* in_sizes, int n_in,
                              void* d_out, int out_size) {
    const float* x  = (const float*)d_in[0];   // (4,64,128,128)
    const float* Wl = (const float*)d_in[1];   // (64,1600,1,1)
    float* out = (float*)d_out;

    // dynamic smem for k_main: t + sparse list
    const int dyn = PIX_ * 4 + CKK_ * 4 + CKK_ * 4;   // 78336 bytes
    static bool attr_set = false;
    if (!attr_set) {
        cudaFuncSetAttribute(k_main, cudaFuncAttributeMaxDynamicSharedMemorySize, dyn);
        attr_set = true;
    }

    k_prep<<<1, 64>>>(Wl);
    k_chansum<<<SPIX_ / 256, 256>>>(x);
    k_box<<<SPIX_ / 256, 256>>>();
    k_main<<<B_ * C_, 256, dyn>>>(x, out);
}

// round 2
// speedup vs baseline: 2.6907x; 2.6907x over previous
#include <cuda_runtime.h>
#include <math_constants.h>

// Problem constants
#define B_      4
#define C_      64
#define H_      128
#define W_      128
#define LOC_    2
#define K_      5
#define KK_     25
#define CKK_    1600
#define PIX_    (H_ * W_)            // 16384
#define PLANE_  (B_ * C_ * PIX_)     // 4,194,304
#define SPIX_   (B_ * PIX_)          // 65536
#define NPLANES_ (B_ * C_)           // 256
#define SEGS_   8
#define SEGPIX_ (PIX_ / SEGS_)       // 2048
#define NT_     256
#define PPT_    (SEGPIX_ / NT_)      // 8 pixels per thread

// Scratch (allocation-free)
__device__ float    g_s[SPIX_];          // channel sum
__device__ float    g_denom[SPIX_];      // max(5x5 box sum, 5)
__device__ float    g_t[PLANE_];         // pre-max normalized tensor
__device__ int      g_nnz[C_];
__device__ float    g_wsum[C_];
__device__ int      g_off[C_ * CKK_];    // c*PIX + dj*W + dk
__device__ int      g_djk[C_ * CKK_];    // ((dj+2)<<16)|(dk+2)
__device__ float    g_w[C_ * CKK_];
__device__ unsigned g_maxkey[NPLANES_];  // monotone float keys

__device__ __forceinline__ unsigned fkey(float f) {
    unsigned b = __float_as_uint(f);
    return (b & 0x80000000u) ? ~b : (b | 0x80000000u);
}
__device__ __forceinline__ float funkey(unsigned k) {
    return (k & 0x80000000u) ? __uint_as_float(k & 0x7FFFFFFFu)
                             : __uint_as_float(~k);
}

// ---------------------------------------------------------------------------
// K1: sparsify W (one warp per output row, ballot compaction: deterministic),
//     precompute gather offsets, row sums; zero per-plane max keys.
// ---------------------------------------------------------------------------
__global__ void k_prep(const float* __restrict__ Wl) {
    const int o = blockIdx.x;            // 64 blocks
    const int lane = threadIdx.x;        // 32 threads
    if (lane < NPLANES_ / C_)            // 4 keys per block
        g_maxkey[o * (NPLANES_ / C_) + lane] = 0u;

    const float* row = Wl + (size_t)o * CKK_;
    int cnt = 0;
    float s = 0.0f;
    for (int base = 0; base < CKK_; base += 32) {
        int k = base + lane;
        float v = row[k];
        s += v;
        unsigned m = __ballot_sync(0xFFFFFFFFu, v != 0.0f);
        if (v != 0.0f) {
            int pos = cnt + __popc(m & ((1u << lane) - 1u));
            int c  = k / KK_;
            int r  = k - c * KK_;
            int j  = r / K_;
            int kk = r - j * K_;
            int dj = j - LOC_, dk = kk - LOC_;
            g_off[o * CKK_ + pos] = c * PIX_ + dj * W_ + dk;
            g_djk[o * CKK_ + pos] = ((dj + LOC_) << 16) | (dk + LOC_);
            g_w  [o * CKK_ + pos] = v;
        }
        cnt += __popc(m);
    }
#pragma unroll
    for (int off = 16; off > 0; off >>= 1)
        s += __shfl_xor_sync(0xFFFFFFFFu, s, off);
    if (lane == 0) { g_nnz[o] = cnt; g_wsum[o] = s; }
}

// ---------------------------------------------------------------------------
// K2: channel sum, float4 vectorized.  idx over SPIX_/4 = 16384.
// ---------------------------------------------------------------------------
__global__ void k_chansum(const float* __restrict__ x) {
    int idx = blockIdx.x * blockDim.x + threadIdx.x;
    int b = idx >> 12;                           // PIX_/4 = 4096 per batch
    const float4* base = (const float4*)x + (size_t)b * C_ * (PIX_ / 4)
                         + (idx & (PIX_ / 4 - 1));
    float4 s = make_float4(0.f, 0.f, 0.f, 0.f);
#pragma unroll 8
    for (int c = 0; c < C_; ++c) {
        float4 v = base[(size_t)c * (PIX_ / 4)];
        s.x += v.x; s.y += v.y; s.z += v.z; s.w += v.w;
    }
    ((float4*)g_s)[idx] = s;
}

// ---------------------------------------------------------------------------
// K3: 5x5 zero-padded box sum of s, clamped at min_support=5
// ---------------------------------------------------------------------------
__global__ void k_box(void) {
    int idx = blockIdx.x * blockDim.x + threadIdx.x;
    int b = idx >> 14;
    int p = idx & (PIX_ - 1);
    int h = p >> 7;
    int w = p & (W_ - 1);
    const float* sp = g_s + b * PIX_;
    float acc = 0.0f;
#pragma unroll
    for (int dj = -LOC_; dj <= LOC_; ++dj) {
        int hs = h + dj;
        if ((unsigned)hs >= H_) continue;
#pragma unroll
        for (int dk = -LOC_; dk <= LOC_; ++dk) {
            int ws = w + dk;
            if ((unsigned)ws >= W_) continue;
            acc += sp[hs * W_ + ws];
        }
    }
    g_denom[idx] = fmaxf(acc, (float)K_);
}

// ---------------------------------------------------------------------------
// K4: sparse gather -> x_lateral, t; per-plane max via atomicMax.
//     grid = NPLANES_ * SEGS_ = 2048 blocks x 256 threads, 8 px/thread.
// ---------------------------------------------------------------------------
__global__ void k_mainA(const float* __restrict__ x, float* __restrict__ out) {
    __shared__ int   s_off[CKK_];
    __shared__ int   s_djk[CKK_];
    __shared__ float s_w[CKK_];
    __shared__ float s_red[NT_ / 32];

    const int bid = blockIdx.x;
    const int bo  = bid >> 3;            // plane 0..255
    const int seg = bid & (SEGS_ - 1);
    const int b   = bo >> 6;
    const int o   = bo & (C_ - 1);
    const int tid = threadIdx.x;

    const int nnz = g_nnz[o];
    for (int e = tid; e < nnz; e += NT_) {
        s_off[e] = g_off[o * CKK_ + e];
        s_djk[e] = g_djk[o * CKK_ + e];
        s_w[e]   = g_w  [o * CKK_ + e];
    }
    __syncthreads();

    const float invw = 1.0f / (1e-10f + g_wsum[o]);
    const float* xb = x + (size_t)b * C_ * PIX_;
    const int pbase = seg * SEGPIX_ + tid;

    float acc[PPT_];
    int   hh[PPT_], ww[PPT_];
#pragma unroll
    for (int i = 0; i < PPT_; ++i) {
        int p = pbase + i * NT_;
        hh[i] = p >> 7;
        ww[i] = p & (W_ - 1);
        acc[i] = 0.0f;
    }

    for (int e = 0; e < nnz; ++e) {
        const int   off = s_off[e];
        const int   djk = s_djk[e];
        const float wv  = s_w[e];
        const int dj = (djk >> 16) - LOC_;
        const int dk = (djk & 0xFFFF) - LOC_;
#pragma unroll
        for (int i = 0; i < PPT_; ++i) {
            int hs = hh[i] + dj;
            int ws = ww[i] + dk;
            if ((unsigned)hs < H_ && (unsigned)ws < W_)
                acc[i] += wv * xb[off + pbase + i * NT_];
        }
    }

    const float* denomb = g_denom + b * PIX_;
    float* out_xl = out + (size_t)bo * PIX_;
    float* tb     = g_t + (size_t)bo * PIX_;

    float lmax = -CUDART_INF_F;
#pragma unroll
    for (int i = 0; i < PPT_; ++i) {
        int p = pbase + i * NT_;
        out_xl[p] = acc[i];
        float tv = acc[i] * invw / denomb[p];
        tb[p] = tv;
        lmax = fmaxf(lmax, tv);
    }

#pragma unroll
    for (int off = 16; off > 0; off >>= 1)
        lmax = fmaxf(lmax, __shfl_xor_sync(0xFFFFFFFFu, lmax, off));
    if ((tid & 31) == 0) s_red[tid >> 5] = lmax;
    __syncthreads();
    if (tid < 32) {
        float v = (tid < NT_ / 32) ? s_red[tid] : -CUDART_INF_F;
#pragma unroll
        for (int off = 16; off > 0; off >>= 1)
            v = fmaxf(v, __shfl_xor_sync(0xFFFFFFFFu, v, off));
        if (tid == 0) atomicMax(&g_maxkey[bo], fkey(v));
    }
}

// ---------------------------------------------------------------------------
// K5: xn = t * invm; bin = (xn^3 >= 0.5). float4 streams.
// ---------------------------------------------------------------------------
__global__ void k_mainB(float* __restrict__ out) {
    int idx = blockIdx.x * blockDim.x + threadIdx.x;   // PLANE_/4 = 1048576
    int plane = idx >> 12;                             // 4096 float4 per plane
    float mx = funkey(g_maxkey[plane]);
    float invm = 1.0f / (1e-10f + mx);

    float4 t4 = ((const float4*)g_t)[idx];
    float4 xn, bn;
    xn.x = t4.x * invm; xn.y = t4.y * invm;
    xn.z = t4.z * invm; xn.w = t4.w * invm;
    bn.x = (xn.x * xn.x * xn.x >= 0.5f) ? 1.0f : 0.0f;
    bn.y = (xn.y * xn.y * xn.y >= 0.5f) ? 1.0f : 0.0f;
    bn.z = (xn.z * xn.z * xn.z >= 0.5f) ? 1.0f : 0.0f;
    bn.w = (xn.w * xn.w * xn.w >= 0.5f) ? 1.0f : 0.0f;

    ((float4*)(out + (size_t)PLANE_))[idx]     = xn;
    ((float4*)(out + (size_t)2 * PLANE_))[idx] = bn;
}

// ---------------------------------------------------------------------------
extern "C" void kernel_launch(void* const* d_in, const int* in_sizes, int n_in,
                              void* d_out, int out_size) {
    const float* x  = (const float*)d_in[0];
    const float* Wl = (const float*)d_in[1];
    float* out = (float*)d_out;

    k_prep<<<C_, 32>>>(Wl);
    k_chansum<<<(SPIX_ / 4) / NT_, NT_>>>(x);       // 64 blocks
    k_box<<<SPIX_ / NT_, NT_>>>();                  // 256 blocks
    k_mainA<<<NPLANES_ * SEGS_, NT_>>>(x, out);     // 2048 blocks
    k_mainB<<<(PLANE_ / 4) / NT_, NT_>>>(out);      // 4096 blocks
}

// round 3
// speedup vs baseline: 3.3259x; 1.2361x over previous
#include <cuda_runtime.h>
#include <math_constants.h>

// Problem constants
#define B_      4
#define C_      64
#define H_      128
#define W_      128
#define LOC_    2
#define K_      5
#define KK_     25
#define CKK_    1600
#define PIX_    (H_ * W_)            // 16384
#define PIX4_   (PIX_ / 4)           // 4096 float4 per plane
#define PLANE_  (B_ * C_ * PIX_)     // 4,194,304
#define SPIX_   (B_ * PIX_)          // 65536
#define NPLANES_ (B_ * C_)           // 256
#define NT_     256
#define SEGS_   16                   // mainA: 16 segs x 256 thr x 4 px = PIX_

// Scratch (allocation-free)
__device__ float    g_s[SPIX_];          // channel sum
__device__ float    g_denom[SPIX_];      // max(5x5 box sum, 5)
__device__ int      g_nnz[C_];
__device__ float    g_wsum[C_];
__device__ int      g_off[C_ * CKK_];    // c*PIX + dj*W + dk
__device__ int      g_dj[C_ * CKK_];
__device__ int      g_dk[C_ * CKK_];
__device__ float    g_w[C_ * CKK_];
__device__ unsigned g_maxkey[NPLANES_];  // monotone float keys

__device__ __forceinline__ unsigned fkey(float f) {
    unsigned b = __float_as_uint(f);
    return (b & 0x80000000u) ? ~b : (b | 0x80000000u);
}
__device__ __forceinline__ float funkey(unsigned k) {
    return (k & 0x80000000u) ? __uint_as_float(k & 0x7FFFFFFFu)
                             : __uint_as_float(~k);
}

// ---------------------------------------------------------------------------
// K1: sparsify W (one warp per output row, ballot compaction: deterministic),
//     precompute gather offsets, row sums; zero per-plane max keys.
// ---------------------------------------------------------------------------
__global__ void k_prep(const float* __restrict__ Wl) {
    const int o = blockIdx.x;            // 64 blocks
    const int lane = threadIdx.x;        // 32 threads
    if (lane < NPLANES_ / C_)
        g_maxkey[o * (NPLANES_ / C_) + lane] = 0u;

    const float* row = Wl + (size_t)o * CKK_;
    int cnt = 0;
    float s = 0.0f;
    for (int base = 0; base < CKK_; base += 32) {
        int k = base + lane;
        float v = row[k];
        s += v;
        unsigned m = __ballot_sync(0xFFFFFFFFu, v != 0.0f);
        if (v != 0.0f) {
            int pos = cnt + __popc(m & ((1u << lane) - 1u));
            int c  = k / KK_;
            int r  = k - c * KK_;
            int j  = r / K_;
            int kk = r - j * K_;
            int dj = j - LOC_, dk = kk - LOC_;
            g_off[o * CKK_ + pos] = c * PIX_ + dj * W_ + dk;
            g_dj [o * CKK_ + pos] = dj;
            g_dk [o * CKK_ + pos] = dk;
            g_w  [o * CKK_ + pos] = v;
        }
        cnt += __popc(m);
    }
#pragma unroll
    for (int off = 16; off > 0; off >>= 1)
        s += __shfl_xor_sync(0xFFFFFFFFu, s, off);
    if (lane == 0) { g_nnz[o] = cnt; g_wsum[o] = s; }
}

// ---------------------------------------------------------------------------
// K2: channel sum, scalar (256 blocks for full-chip parallelism)
// ---------------------------------------------------------------------------
__global__ void k_chansum(const float* __restrict__ x) {
    int idx = blockIdx.x * blockDim.x + threadIdx.x;   // 0..SPIX_-1
    int b = idx >> 14;
    int p = idx & (PIX_ - 1);
    const float* base = x + (size_t)b * C_ * PIX_ + p;
    float s = 0.0f;
#pragma unroll 16
    for (int c = 0; c < C_; ++c) s += base[(size_t)c * PIX_];
    g_s[idx] = s;
}

// ---------------------------------------------------------------------------
// K3: 5x5 zero-padded box sum of s, clamped at min_support=5
// ---------------------------------------------------------------------------
__global__ void k_box(void) {
    int idx = blockIdx.x * blockDim.x + threadIdx.x;
    int b = idx >> 14;
    int p = idx & (PIX_ - 1);
    int h = p >> 7;
    int w = p & (W_ - 1);
    const float* sp = g_s + b * PIX_;
    float acc = 0.0f;
#pragma unroll
    for (int dj = -LOC_; dj <= LOC_; ++dj) {
        int hs = h + dj;
        if ((unsigned)hs >= H_) continue;
#pragma unroll
        for (int dk = -LOC_; dk <= LOC_; ++dk) {
            int ws = w + dk;
            if ((unsigned)ws >= W_) continue;
            acc += sp[hs * W_ + ws];
        }
    }
    g_denom[idx] = fmaxf(acc, (float)K_);
}

// ---------------------------------------------------------------------------
// K4 (mainA): sparse gather -> x_lateral (float4); per-plane max via atomicMax.
//   grid = NPLANES_ * SEGS_ = 4096 blocks x 256 threads, 4 consecutive px/thr.
//   All 4 pixels share a row (W%4==0), so hs bounds hoist per tap.
//   dk==0 taps use an aligned float4 gather.
// ---------------------------------------------------------------------------
__global__ void k_mainA(const float* __restrict__ x, float* __restrict__ out) {
    __shared__ int   s_off[CKK_];
    __shared__ int   s_dj[CKK_];
    __shared__ int   s_dk[CKK_];
    __shared__ float s_w[CKK_];
    __shared__ float s_red[NT_ / 32];

    const int bid = blockIdx.x;
    const int bo  = bid >> 4;            // plane 0..255
    const int seg = bid & (SEGS_ - 1);
    const int b   = bo >> 6;
    const int o   = bo & (C_ - 1);
    const int tid = threadIdx.x;

    const int nnz = g_nnz[o];
    for (int e = tid; e < nnz; e += NT_) {
        s_off[e] = g_off[o * CKK_ + e];
        s_dj[e]  = g_dj [o * CKK_ + e];
        s_dk[e]  = g_dk [o * CKK_ + e];
        s_w[e]   = g_w  [o * CKK_ + e];
    }
    __syncthreads();

    const float invw = 1.0f / (1e-10f + g_wsum[o]);
    const float* xb = x + (size_t)b * C_ * PIX_;

    const int f4 = seg * NT_ + tid;      // float4 index within plane, 0..4095
    const int p0 = f4 * 4;               // first pixel
    const int h  = p0 >> 7;
    const int w0 = p0 & (W_ - 1);        // 0..124, multiple of 4

    float acc0 = 0.f, acc1 = 0.f, acc2 = 0.f, acc3 = 0.f;

    for (int e = 0; e < nnz; ++e) {
        const int hs = h + s_dj[e];
        if ((unsigned)hs >= H_) continue;
        const int   dk  = s_dk[e];
        const float wv  = s_w[e];
        const float* src = xb + s_off[e] + p0;
        if (dk == 0) {
            float4 v = *(const float4*)src;          // aligned
            acc0 += wv * v.x; acc1 += wv * v.y;
            acc2 += wv * v.z; acc3 += wv * v.w;
        } else {
            if ((unsigned)(w0 + 0 + dk) < W_) acc0 += wv * src[0];
            if ((unsigned)(w0 + 1 + dk) < W_) acc1 += wv * src[1];
            if ((unsigned)(w0 + 2 + dk) < W_) acc2 += wv * src[2];
            if ((unsigned)(w0 + 3 + dk) < W_) acc3 += wv * src[3];
        }
    }

    // write x_lateral
    ((float4*)(out + (size_t)bo * PIX_))[f4] = make_float4(acc0, acc1, acc2, acc3);

    // t = xl * invw / denom ; local max
    float4 d4 = ((const float4*)(g_denom + b * PIX_))[f4];
    float t0 = acc0 * invw / d4.x;
    float t1 = acc1 * invw / d4.y;
    float t2 = acc2 * invw / d4.z;
    float t3 = acc3 * invw / d4.w;
    float lmax = fmaxf(fmaxf(t0, t1), fmaxf(t2, t3));

#pragma unroll
    for (int off = 16; off > 0; off >>= 1)
        lmax = fmaxf(lmax, __shfl_xor_sync(0xFFFFFFFFu, lmax, off));
    if ((tid & 31) == 0) s_red[tid >> 5] = lmax;
    __syncthreads();
    if (tid < 32) {
        float v = (tid < NT_ / 32) ? s_red[tid] : -CUDART_INF_F;
#pragma unroll
        for (int off = 16; off > 0; off >>= 1)
            v = fmaxf(v, __shfl_xor_sync(0xFFFFFFFFu, v, off));
        if (tid == 0) atomicMax(&g_maxkey[bo], fkey(v));
    }
}

// ---------------------------------------------------------------------------
// K5 (mainB): recompute t from x_lateral (L2-hot) + denom, then
//   xn = t * invm; bin = (xn^3 >= 0.5). float4 streams, no g_t scratch.
// ---------------------------------------------------------------------------
__global__ void k_mainB(float* __restrict__ out) {
    int idx = blockIdx.x * blockDim.x + threadIdx.x;   // 0..PLANE_/4-1
    int plane = idx >> 12;                             // 4096 f4 per plane
    int b = plane >> 6;
    int o = plane & (C_ - 1);

    float invw = 1.0f / (1e-10f + g_wsum[o]);
    float mx = funkey(g_maxkey[plane]);
    float invm = 1.0f / (1e-10f + mx);
    float f = invw;                                    // applied before /denom

    float4 xl = ((const float4*)out)[idx];
    float4 d4 = ((const float4*)(g_denom + b * PIX_))[idx & (PIX4_ - 1)];

    float t0 = xl.x * f / d4.x;
    float t1 = xl.y * f / d4.y;
    float t2 = xl.z * f / d4.z;
    float t3 = xl.w * f / d4.w;

    float4 xn, bn;
    xn.x = t0 * invm; xn.y = t1 * invm;
    xn.z = t2 * invm; xn.w = t3 * invm;
    bn.x = (xn.x * xn.x * xn.x >= 0.5f) ? 1.0f : 0.0f;
    bn.y = (xn.y * xn.y * xn.y >= 0.5f) ? 1.0f : 0.0f;
    bn.z = (xn.z * xn.z * xn.z >= 0.5f) ? 1.0f : 0.0f;
    bn.w = (xn.w * xn.w * xn.w >= 0.5f) ? 1.0f : 0.0f;

    ((float4*)(out + (size_t)PLANE_))[idx]     = xn;
    ((float4*)(out + (size_t)2 * PLANE_))[idx] = bn;
}

// ---------------------------------------------------------------------------
extern "C" void kernel_launch(void* const* d_in, const int* in_sizes, int n_in,
                              void* d_out, int out_size) {
    const float* x  = (const float*)d_in[0];
    const float* Wl = (const float*)d_in[1];
    float* out = (float*)d_out;

    k_prep<<<C_, 32>>>(Wl);
    k_chansum<<<SPIX_ / NT_, NT_>>>(x);             // 256 blocks
    k_box<<<SPIX_ / NT_, NT_>>>();                  // 256 blocks
    k_mainA<<<NPLANES_ * SEGS_, NT_>>>(x, out);     // 4096 blocks
    k_mainB<<<(PLANE_ / 4) / NT_, NT_>>>(out);      // 4096 blocks
}

// round 4
// speedup vs baseline: 4.0324x; 1.2124x over previous
#include <cuda_runtime.h>
#include <math_constants.h>

// Problem constants
#define B_      4
#define C_      64
#define H_      128
#define W_      128
#define LOC_    2
#define K_      5
#define KK_     25
#define CKK_    1600
#define PIX_    (H_ * W_)            // 16384
#define PIX4_   (PIX_ / 4)           // 4096
#define PIX2_   (PIX_ / 2)           // 8192
#define PLANE_  (B_ * C_ * PIX_)     // 4,194,304
#define SPIX_   (B_ * PIX_)          // 65536
#define NPLANES_ (B_ * C_)           // 256
#define NT_     256
#define SEGS_   16                   // mainA: 16 segs x 256 thr x 4 px = PIX_

// Scratch (allocation-free)
__device__ float    g_s[SPIX_];          // channel sum
__device__ float    g_rdenom[SPIX_];     // 1 / max(5x5 box sum, 5)
__device__ int      g_nnz[C_];
__device__ float    g_invw[C_];          // 1 / (1e-10 + row sum)
__device__ int      g_off[C_ * CKK_];    // c*PIX + dj*W + dk
__device__ int      g_dj[C_ * CKK_];
__device__ int      g_dk[C_ * CKK_];
__device__ float    g_w[C_ * CKK_];
__device__ unsigned g_maxkey[NPLANES_];  // monotone float keys

__device__ __forceinline__ unsigned fkey(float f) {
    unsigned b = __float_as_uint(f);
    return (b & 0x80000000u) ? ~b : (b | 0x80000000u);
}
__device__ __forceinline__ float funkey(unsigned k) {
    return (k & 0x80000000u) ? __uint_as_float(k & 0x7FFFFFFFu)
                             : __uint_as_float(~k);
}

// ---------------------------------------------------------------------------
// K1: sparsify W (one warp per output row, ballot compaction: deterministic),
//     precompute gather offsets, 1/(1e-10+rowsum); zero per-plane max keys.
// ---------------------------------------------------------------------------
__global__ void k_prep(const float* __restrict__ Wl) {
    const int o = blockIdx.x;            // 64 blocks
    const int lane = threadIdx.x;        // 32 threads
    if (lane < NPLANES_ / C_)
        g_maxkey[o * (NPLANES_ / C_) + lane] = 0u;

    const float* row = Wl + (size_t)o * CKK_;
    int cnt = 0;
    float s = 0.0f;
    for (int base = 0; base < CKK_; base += 32) {
        int k = base + lane;
        float v = row[k];
        s += v;
        unsigned m = __ballot_sync(0xFFFFFFFFu, v != 0.0f);
        if (v != 0.0f) {
            int pos = cnt + __popc(m & ((1u << lane) - 1u));
            int c  = k / KK_;
            int r  = k - c * KK_;
            int j  = r / K_;
            int kk = r - j * K_;
            int dj = j - LOC_, dk = kk - LOC_;
            g_off[o * CKK_ + pos] = c * PIX_ + dj * W_ + dk;
            g_dj [o * CKK_ + pos] = dj;
            g_dk [o * CKK_ + pos] = dk;
            g_w  [o * CKK_ + pos] = v;
        }
        cnt += __popc(m);
    }
#pragma unroll
    for (int off = 16; off > 0; off >>= 1)
        s += __shfl_xor_sync(0xFFFFFFFFu, s, off);
    if (lane == 0) {
        g_nnz[o] = cnt;
        g_invw[o] = 1.0f / (1e-10f + s);
    }
}

// ---------------------------------------------------------------------------
// K2: channel sum, float2, grid = 256 blocks x 128 threads (full chip)
// ---------------------------------------------------------------------------
__global__ void k_chansum(const float* __restrict__ x) {
    int idx = blockIdx.x * blockDim.x + threadIdx.x;   // 0..SPIX_/2-1
    int b = idx >> 13;                                  // PIX2_ per batch
    const float2* base = (const float2*)x + (size_t)b * C_ * PIX2_
                         + (idx & (PIX2_ - 1));
    float2 s = make_float2(0.f, 0.f);
#pragma unroll 16
    for (int c = 0; c < C_; ++c) {
        float2 v = base[(size_t)c * PIX2_];
        s.x += v.x; s.y += v.y;
    }
    ((float2*)g_s)[idx] = s;
}

// ---------------------------------------------------------------------------
// K3: 5x5 zero-padded box sum of s, rdenom = 1/max(acc, 5)
// ---------------------------------------------------------------------------
__global__ void k_box(void) {
    int idx = blockIdx.x * blockDim.x + threadIdx.x;
    int b = idx >> 14;
    int p = idx & (PIX_ - 1);
    int h = p >> 7;
    int w = p & (W_ - 1);
    const float* sp = g_s + b * PIX_;
    float acc = 0.0f;
#pragma unroll
    for (int dj = -LOC_; dj <= LOC_; ++dj) {
        int hs = h + dj;
        if ((unsigned)hs >= H_) continue;
#pragma unroll
        for (int dk = -LOC_; dk <= LOC_; ++dk) {
            int ws = w + dk;
            if ((unsigned)ws >= W_) continue;
            acc += sp[hs * W_ + ws];
        }
    }
    g_rdenom[idx] = 1.0f / fmaxf(acc, (float)K_);
}

// ---------------------------------------------------------------------------
// K4 (mainA): sparse gather -> x_lateral; per-plane max via warp atomicMax.
//   grid = 4096 blocks x 256 threads, 4 consecutive px/thread (1 float4).
//   NO shared memory, NO __syncthreads. Sparse list read uniformly from L1.
// ---------------------------------------------------------------------------
__global__ void __launch_bounds__(NT_) k_mainA(const float* __restrict__ x,
                                               float* __restrict__ out) {
    const int bid = blockIdx.x;
    const int bo  = bid >> 4;            // plane 0..255
    const int seg = bid & (SEGS_ - 1);
    const int b   = bo >> 6;
    const int o   = bo & (C_ - 1);
    const int tid = threadIdx.x;

    const int   nnz  = g_nnz[o];
    const float invw = g_invw[o];
    const float* xb = x + (size_t)b * C_ * PIX_;

    const int f4 = seg * NT_ + tid;      // float4 index in plane
    const int p0 = f4 * 4;
    const int h  = p0 >> 7;
    const int w0 = p0 & (W_ - 1);

    float acc0 = 0.f, acc1 = 0.f, acc2 = 0.f, acc3 = 0.f;

    const int lbase = o * CKK_;
    for (int e = 0; e < nnz; ++e) {
        const int   off = __ldg(g_off + lbase + e);
        const int   dj  = __ldg(g_dj  + lbase + e);
        const int   dk  = __ldg(g_dk  + lbase + e);
        const float wv  = __ldg(g_w   + lbase + e);
        const int hs = h + dj;
        if ((unsigned)hs >= H_) continue;
        const float* src = xb + off + p0;
        if (dk == 0) {
            float4 v = *(const float4*)src;          // aligned
            acc0 += wv * v.x; acc1 += wv * v.y;
            acc2 += wv * v.z; acc3 += wv * v.w;
        } else {
            if ((unsigned)(w0 + 0 + dk) < W_) acc0 += wv * src[0];
            if ((unsigned)(w0 + 1 + dk) < W_) acc1 += wv * src[1];
            if ((unsigned)(w0 + 2 + dk) < W_) acc2 += wv * src[2];
            if ((unsigned)(w0 + 3 + dk) < W_) acc3 += wv * src[3];
        }
    }

    // write x_lateral
    ((float4*)(out + (size_t)bo * PIX_))[f4] = make_float4(acc0, acc1, acc2, acc3);

    // t = xl * invw * rdenom ; local max
    float4 r4 = ((const float4*)(g_rdenom + b * PIX_))[f4];
    float t0 = acc0 * invw * r4.x;
    float t1 = acc1 * invw * r4.y;
    float t2 = acc2 * invw * r4.z;
    float t3 = acc3 * invw * r4.w;
    float lmax = fmaxf(fmaxf(t0, t1), fmaxf(t2, t3));

#pragma unroll
    for (int off = 16; off > 0; off >>= 1)
        lmax = fmaxf(lmax, __shfl_xor_sync(0xFFFFFFFFu, lmax, off));
    if ((tid & 31) == 0)
        atomicMax(&g_maxkey[bo], fkey(lmax));
}

// ---------------------------------------------------------------------------
// K5 (mainB): xn = xl * rdenom * (invw*invm); bin = (xn^3 >= 0.5).
// ---------------------------------------------------------------------------
__global__ void __launch_bounds__(NT_) k_mainB(float* __restrict__ out) {
    int idx = blockIdx.x * blockDim.x + threadIdx.x;   // 0..PLANE_/4-1
    int plane = idx >> 12;
    int b = plane >> 6;
    int o = plane & (C_ - 1);

    float mx = funkey(g_maxkey[plane]);
    float scale = g_invw[o] / (1e-10f + mx);           // uniform per block

    float4 xl = ((const float4*)out)[idx];
    float4 r4 = ((const float4*)(g_rdenom + b * PIX_))[idx & (PIX4_ - 1)];

    float4 xn, bn;
    xn.x = xl.x * r4.x * scale;
    xn.y = xl.y * r4.y * scale;
    xn.z = xl.z * r4.z * scale;
    xn.w = xl.w * r4.w * scale;
    bn.x = (xn.x * xn.x * xn.x >= 0.5f) ? 1.0f : 0.0f;
    bn.y = (xn.y * xn.y * xn.y >= 0.5f) ? 1.0f : 0.0f;
    bn.z = (xn.z * xn.z * xn.z >= 0.5f) ? 1.0f : 0.0f;
    bn.w = (xn.w * xn.w * xn.w >= 0.5f) ? 1.0f : 0.0f;

    ((float4*)(out + (size_t)PLANE_))[idx]     = xn;
    ((float4*)(out + (size_t)2 * PLANE_))[idx] = bn;
}

// ---------------------------------------------------------------------------
extern "C" void kernel_launch(void* const* d_in, const int* in_sizes, int n_in,
                              void* d_out, int out_size) {
    const float* x  = (const float*)d_in[0];
    const float* Wl = (const float*)d_in[1];
    float* out = (float*)d_out;

    k_prep<<<C_, 32>>>(Wl);
    k_chansum<<<SPIX_ / 2 / 128, 128>>>(x);         // 256 blocks x 128
    k_box<<<SPIX_ / NT_, NT_>>>();                  // 256 blocks
    k_mainA<<<NPLANES_ * SEGS_, NT_>>>(x, out);     // 4096 blocks
    k_mainB<<<(PLANE_ / 4) / NT_, NT_>>>(out);      // 4096 blocks
}

// round 5
// speedup vs baseline: 5.2830x; 1.3101x over previous
#include <cuda_runtime.h>
#include <math_constants.h>

// Problem constants
#define B_      4
#define C_      64
#define H_      128
#define W_      128
#define LOC_    2
#define K_      5
#define KK_     25
#define CKK_    1600
#define PIX_    (H_ * W_)            // 16384
#define PIX4_   (PIX_ / 4)           // 4096
#define PIX2_   (PIX_ / 2)           // 8192
#define PLANE_  (B_ * C_ * PIX_)     // 4,194,304
#define SPIX_   (B_ * PIX_)          // 65536
#define NPLANES_ (B_ * C_)           // 256
#define FNT_    1024                 // fused kernel threads
#define FPT_    4                    // float4 per thread (FNT_*FPT_ == PIX4_)

// Scratch (allocation-free)
__device__ float    g_s[SPIX_];          // channel sum
__device__ float    g_rdenom[SPIX_];     // 1 / max(5x5 box sum, 5)
__device__ int      g_nnz[C_];
__device__ float    g_invw[C_];          // 1 / (1e-10 + row sum)
__device__ int      g_off[C_ * CKK_];    // c*PIX + dj*W + dk
__device__ int      g_dj[C_ * CKK_];
__device__ int      g_dk[C_ * CKK_];
__device__ float    g_w[C_ * CKK_];

// ---------------------------------------------------------------------------
// K1: sparsify W (one warp per output row, ballot compaction: deterministic),
//     precompute gather offsets, 1/(1e-10+rowsum).
// ---------------------------------------------------------------------------
__global__ void k_prep(const float* __restrict__ Wl) {
    const int o = blockIdx.x;            // 64 blocks
    const int lane = threadIdx.x;        // 32 threads

    const float* row = Wl + (size_t)o * CKK_;
    int cnt = 0;
    float s = 0.0f;
    for (int base = 0; base < CKK_; base += 32) {
        int k = base + lane;
        float v = row[k];
        s += v;
        unsigned m = __ballot_sync(0xFFFFFFFFu, v != 0.0f);
        if (v != 0.0f) {
            int pos = cnt + __popc(m & ((1u << lane) - 1u));
            int c  = k / KK_;
            int r  = k - c * KK_;
            int j  = r / K_;
            int kk = r - j * K_;
            int dj = j - LOC_, dk = kk - LOC_;
            g_off[o * CKK_ + pos] = c * PIX_ + dj * W_ + dk;
            g_dj [o * CKK_ + pos] = dj;
            g_dk [o * CKK_ + pos] = dk;
            g_w  [o * CKK_ + pos] = v;
        }
        cnt += __popc(m);
    }
#pragma unroll
    for (int off = 16; off > 0; off >>= 1)
        s += __shfl_xor_sync(0xFFFFFFFFu, s, off);
    if (lane == 0) {
        g_nnz[o] = cnt;
        g_invw[o] = 1.0f / (1e-10f + s);
    }
}

// ---------------------------------------------------------------------------
// K2: channel sum, float2, grid = 256 blocks x 128 threads
// ---------------------------------------------------------------------------
__global__ void k_chansum(const float* __restrict__ x) {
    int idx = blockIdx.x * blockDim.x + threadIdx.x;   // 0..SPIX_/2-1
    int b = idx >> 13;
    const float2* base = (const float2*)x + (size_t)b * C_ * PIX2_
                         + (idx & (PIX2_ - 1));
    float2 s = make_float2(0.f, 0.f);
#pragma unroll 16
    for (int c = 0; c < C_; ++c) {
        float2 v = base[(size_t)c * PIX2_];
        s.x += v.x; s.y += v.y;
    }
    ((float2*)g_s)[idx] = s;
}

// ---------------------------------------------------------------------------
// K3: 5x5 zero-padded box sum of s, rdenom = 1/max(acc, 5)
// ---------------------------------------------------------------------------
__global__ void k_box(void) {
    int idx = blockIdx.x * blockDim.x + threadIdx.x;
    int b = idx >> 14;
    int p = idx & (PIX_ - 1);
    int h = p >> 7;
    int w = p & (W_ - 1);
    const float* sp = g_s + b * PIX_;
    float acc = 0.0f;
#pragma unroll
    for (int dj = -LOC_; dj <= LOC_; ++dj) {
        int hs = h + dj;
        if ((unsigned)hs >= H_) continue;
#pragma unroll
        for (int dk = -LOC_; dk <= LOC_; ++dk) {
            int ws = w + dk;
            if ((unsigned)ws >= W_) continue;
            acc += sp[hs * W_ + ws];
        }
    }
    g_rdenom[idx] = 1.0f / fmaxf(acc, (float)K_);
}

// ---------------------------------------------------------------------------
// K4 (fused): one block per (b,o) plane, 1024 threads, 4 float4/thread.
//   Phase 1: sparse gather -> xl (write), t kept in registers, local max.
//   Block max reduction (no global atomics, no second kernel).
//   Phase 2: xn = t*invm, bin = (xn^3 >= 0.5), write.
// ---------------------------------------------------------------------------
__global__ void __launch_bounds__(FNT_) k_fused(const float* __restrict__ x,
                                                float* __restrict__ out) {
    __shared__ float s_red[FNT_ / 32];
    __shared__ float s_max;

    const int bo  = blockIdx.x;          // plane 0..255
    const int b   = bo >> 6;
    const int o   = bo & (C_ - 1);
    const int tid = threadIdx.x;

    const int   nnz  = g_nnz[o];
    const float invw = g_invw[o];
    const float* xb = x + (size_t)b * C_ * PIX_;
    const int lbase = o * CKK_;

    float4* out_xl = (float4*)(out + (size_t)bo * PIX_);
    const float4* rdn = (const float4*)(g_rdenom + b * PIX_);

    float acc[FPT_][4];
    int hh[FPT_], ww0[FPT_];
#pragma unroll
    for (int i = 0; i < FPT_; ++i) {
        int p0 = (tid + i * FNT_) * 4;
        hh[i]  = p0 >> 7;
        ww0[i] = p0 & (W_ - 1);
        acc[i][0] = acc[i][1] = acc[i][2] = acc[i][3] = 0.0f;
    }

    for (int e = 0; e < nnz; ++e) {
        const int   off = __ldg(g_off + lbase + e);
        const int   dj  = __ldg(g_dj  + lbase + e);
        const int   dk  = __ldg(g_dk  + lbase + e);
        const float wv  = __ldg(g_w   + lbase + e);
#pragma unroll
        for (int i = 0; i < FPT_; ++i) {
            const int hs = hh[i] + dj;
            if ((unsigned)hs >= H_) continue;
            const float* src = xb + off + (tid + i * FNT_) * 4;
            if (dk == 0) {
                float4 v = *(const float4*)src;          // aligned
                acc[i][0] += wv * v.x; acc[i][1] += wv * v.y;
                acc[i][2] += wv * v.z; acc[i][3] += wv * v.w;
            } else {
                if ((unsigned)(ww0[i] + 0 + dk) < W_) acc[i][0] += wv * src[0];
                if ((unsigned)(ww0[i] + 1 + dk) < W_) acc[i][1] += wv * src[1];
                if ((unsigned)(ww0[i] + 2 + dk) < W_) acc[i][2] += wv * src[2];
                if ((unsigned)(ww0[i] + 3 + dk) < W_) acc[i][3] += wv * src[3];
            }
        }
    }

    // write x_lateral, compute t in registers, local max
    float t[FPT_][4];
    float lmax = -CUDART_INF_F;
#pragma unroll
    for (int i = 0; i < FPT_; ++i) {
        int f4 = tid + i * FNT_;
        out_xl[f4] = make_float4(acc[i][0], acc[i][1], acc[i][2], acc[i][3]);
        float4 r4 = rdn[f4];
        t[i][0] = acc[i][0] * invw * r4.x;
        t[i][1] = acc[i][1] * invw * r4.y;
        t[i][2] = acc[i][2] * invw * r4.z;
        t[i][3] = acc[i][3] * invw * r4.w;
        lmax = fmaxf(lmax, fmaxf(fmaxf(t[i][0], t[i][1]), fmaxf(t[i][2], t[i][3])));
    }

    // block max reduction (1024 threads)
#pragma unroll
    for (int off = 16; off > 0; off >>= 1)
        lmax = fmaxf(lmax, __shfl_xor_sync(0xFFFFFFFFu, lmax, off));
    if ((tid & 31) == 0) s_red[tid >> 5] = lmax;
    __syncthreads();
    if (tid < 32) {
        float v = s_red[tid];
#pragma unroll
        for (int off = 16; off > 0; off >>= 1)
            v = fmaxf(v, __shfl_xor_sync(0xFFFFFFFFu, v, off));
        if (tid == 0) s_max = v;
    }
    __syncthreads();

    const float invm = 1.0f / (1e-10f + s_max);
    float4* out_xn  = (float4*)(out + (size_t)PLANE_     + (size_t)bo * PIX_);
    float4* out_bin = (float4*)(out + (size_t)2 * PLANE_ + (size_t)bo * PIX_);
#pragma unroll
    for (int i = 0; i < FPT_; ++i) {
        int f4 = tid + i * FNT_;
        float4 xn, bn;
        xn.x = t[i][0] * invm; xn.y = t[i][1] * invm;
        xn.z = t[i][2] * invm; xn.w = t[i][3] * invm;
        bn.x = (xn.x * xn.x * xn.x >= 0.5f) ? 1.0f : 0.0f;
        bn.y = (xn.y * xn.y * xn.y >= 0.5f) ? 1.0f : 0.0f;
        bn.z = (xn.z * xn.z * xn.z >= 0.5f) ? 1.0f : 0.0f;
        bn.w = (xn.w * xn.w * xn.w >= 0.5f) ? 1.0f : 0.0f;
        out_xn[f4]  = xn;
        out_bin[f4] = bn;
    }
}

// ---------------------------------------------------------------------------
extern "C" void kernel_launch(void* const* d_in, const int* in_sizes, int n_in,
                              void* d_out, int out_size) {
    const float* x  = (const float*)d_in[0];
    const float* Wl = (const float*)d_in[1];
    float* out = (float*)d_out;

    k_prep<<<C_, 32>>>(Wl);
    k_chansum<<<SPIX_ / 2 / 128, 128>>>(x);         // 256 blocks x 128
    k_box<<<SPIX_ / 256, 256>>>();                  // 256 blocks
    k_fused<<<NPLANES_, FNT_>>>(x, out);            // 256 blocks x 1024
}

// round 11
// speedup vs baseline: 5.5446x; 1.0495x over previous
#include <cuda_runtime.h>
#include <math_constants.h>
#include <cstdint>

// Problem constants
#define B_      4
#define C_      64
#define H_      128
#define W_      128
#define LOC_    2
#define K_      5
#define KK_     25
#define CKK_    1600
#define PIX_    (H_ * W_)            // 16384
#define PIX4_   (PIX_ / 4)           // 4096
#define PLANE_  (B_ * C_ * PIX_)     // 4,194,304
#define SPIX_   (B_ * PIX_)          // 65536
#define NPLANES_ (B_ * C_)           // 256
#define FNT_    1024                 // fused threads per CTA
#define FPT_    4                    // float4 chunks per thread

// Scratch (allocation-free)
__device__ float    g_s[SPIX_];          // channel sum
__device__ float    g_rdenom[SPIX_];     // 1 / max(5x5 box sum, 5)
__device__ int      g_nnz[C_];
__device__ float    g_invw[C_];          // 1 / (1e-10 + row sum)
__device__ int      g_off[C_ * CKK_];    // c*PIX + dj*W + dk
__device__ int      g_dj[C_ * CKK_];
__device__ int      g_dk[C_ * CKK_];
__device__ float    g_w[C_ * CKK_];

// ---------------------------------------------------------------------------
// K1 (support): heterogeneous.
//   blocks 0..63   : sparsify W row o=blockIdx.x (warp 0 only)
//   blocks 64..319 : channel sum, 256 px per block (scalar, coalesced)
// ---------------------------------------------------------------------------
__global__ void __launch_bounds__(256) k_support(const float* __restrict__ Wl,
                                                 const float* __restrict__ x) {
    const int tid = threadIdx.x;
    if (blockIdx.x < 64) {
        if (tid >= 32) return;
        const int o = blockIdx.x;
        const int lane = tid;
        const float* row = Wl + (size_t)o * CKK_;
        int cnt = 0;
        float s = 0.0f;
        for (int base = 0; base < CKK_; base += 32) {
            int k = base + lane;
            float v = row[k];
            s += v;
            unsigned m = __ballot_sync(0xFFFFFFFFu, v != 0.0f);
            if (v != 0.0f) {
                int pos = cnt + __popc(m & ((1u << lane) - 1u));
                int c  = k / KK_;
                int r  = k - c * KK_;
                int j  = r / K_;
                int kk = r - j * K_;
                int dj = j - LOC_, dk = kk - LOC_;
                g_off[o * CKK_ + pos] = c * PIX_ + dj * W_ + dk;
                g_dj [o * CKK_ + pos] = dj;
                g_dk [o * CKK_ + pos] = dk;
                g_w  [o * CKK_ + pos] = v;
            }
            cnt += __popc(m);
        }
#pragma unroll
        for (int off = 16; off > 0; off >>= 1)
            s += __shfl_xor_sync(0xFFFFFFFFu, s, off);
        if (lane == 0) {
            g_nnz[o] = cnt;
            g_invw[o] = 1.0f / (1e-10f + s);
        }
    } else {
        const int idx = (blockIdx.x - 64) * 256 + tid;   // 0..SPIX_-1
        const int b = idx >> 14;
        const int p = idx & (PIX_ - 1);
        const float* base = x + (size_t)b * C_ * PIX_ + p;
        float s = 0.0f;
#pragma unroll 16
        for (int c = 0; c < C_; ++c) s += base[(size_t)c * PIX_];
        g_s[idx] = s;
    }
}

// ---------------------------------------------------------------------------
// K2: 5x5 zero-padded box sum of s, rdenom = 1/max(acc, 5)
// ---------------------------------------------------------------------------
__global__ void __launch_bounds__(256) k_box(void) {
    int idx = blockIdx.x * blockDim.x + threadIdx.x;
    int b = idx >> 14;
    int p = idx & (PIX_ - 1);
    int h = p >> 7;
    int w = p & (W_ - 1);
    const float* sp = g_s + b * PIX_;
    float acc = 0.0f;
#pragma unroll
    for (int dj = -LOC_; dj <= LOC_; ++dj) {
        int hs = h + dj;
        if ((unsigned)hs >= H_) continue;
#pragma unroll
        for (int dk = -LOC_; dk <= LOC_; ++dk) {
            int ws = w + dk;
            if ((unsigned)ws >= W_) continue;
            acc += sp[hs * W_ + ws];
        }
    }
    g_rdenom[idx] = 1.0f / fmaxf(acc, (float)K_);
}

// ---------------------------------------------------------------------------
// K3 (fused): one CTA per (b,o) plane, 1024 threads, 2 CTAs/SM (all 256
//   blocks resident in one wave). Minimal register liveness:
//   Phase 1 (per 4-px chunk): gather xl, write it, fold t into running max.
//   Block max barrier.
//   Phase 2: reload xl (L2-hot) + rdenom, recompute t identically, write
//   xn and bin. No state carried across the barrier except lmax/invm.
// ---------------------------------------------------------------------------
__global__ void __launch_bounds__(FNT_, 2) k_fused(const float* __restrict__ x,
                                                   float* __restrict__ out) {
    __shared__ float s_red[FNT_ / 32];
    __shared__ float s_max;

    const int bo  = blockIdx.x;          // plane 0..255
    const int b   = bo >> 6;
    const int o   = bo & (C_ - 1);
    const int tid = threadIdx.x;

    const int   nnz  = g_nnz[o];
    const float invw = g_invw[o];
    const float* xb = x + (size_t)b * C_ * PIX_;
    const int lbase = o * CKK_;

    float4* out_xl = (float4*)(out + (size_t)bo * PIX_);
    const float4* rdn = (const float4*)(g_rdenom + b * PIX_);

    float lmax = -CUDART_INF_F;

#pragma unroll
    for (int i = 0; i < FPT_; ++i) {
        const int f4 = tid + i * FNT_;
        const int p0 = f4 * 4;
        const int h  = p0 >> 7;
        const int w0 = p0 & (W_ - 1);

        float a0 = 0.f, a1 = 0.f, a2 = 0.f, a3 = 0.f;
        for (int e = 0; e < nnz; ++e) {
            const int   off = __ldg(g_off + lbase + e);
            const int   dj  = __ldg(g_dj  + lbase + e);
            const int   dk  = __ldg(g_dk  + lbase + e);
            const float wv  = __ldg(g_w   + lbase + e);
            const int hs = h + dj;
            if ((unsigned)hs >= H_) continue;
            const float* src = xb + off + p0;
            if (dk == 0) {
                float4 v = *(const float4*)src;          // aligned
                a0 += wv * v.x; a1 += wv * v.y;
                a2 += wv * v.z; a3 += wv * v.w;
            } else {
                if ((unsigned)(w0 + 0 + dk) < W_) a0 += wv * src[0];
                if ((unsigned)(w0 + 1 + dk) < W_) a1 += wv * src[1];
                if ((unsigned)(w0 + 2 + dk) < W_) a2 += wv * src[2];
                if ((unsigned)(w0 + 3 + dk) < W_) a3 += wv * src[3];
            }
        }

        out_xl[f4] = make_float4(a0, a1, a2, a3);
        float4 r4 = rdn[f4];
        float t0 = a0 * invw * r4.x;
        float t1 = a1 * invw * r4.y;
        float t2 = a2 * invw * r4.z;
        float t3 = a3 * invw * r4.w;
        lmax = fmaxf(lmax, fmaxf(fmaxf(t0, t1), fmaxf(t2, t3)));
    }

    // block max reduction
#pragma unroll
    for (int off = 16; off > 0; off >>= 1)
        lmax = fmaxf(lmax, __shfl_xor_sync(0xFFFFFFFFu, lmax, off));
    if ((tid & 31) == 0) s_red[tid >> 5] = lmax;
    __syncthreads();
    if (tid < 32) {
        float v = s_red[tid];
#pragma unroll
        for (int off = 16; off > 0; off >>= 1)
            v = fmaxf(v, __shfl_xor_sync(0xFFFFFFFFu, v, off));
        if (tid == 0) s_max = v;
    }
    __syncthreads();

    const float invm = 1.0f / (1e-10f + s_max);
    float4* out_xn  = (float4*)(out + (size_t)PLANE_     + (size_t)bo * PIX_);
    float4* out_bin = (float4*)(out + (size_t)2 * PLANE_ + (size_t)bo * PIX_);

#pragma unroll
    for (int i = 0; i < FPT_; ++i) {
        const int f4 = tid + i * FNT_;
        float4 xl = out_xl[f4];                 // L2-hot reload
        float4 r4 = rdn[f4];
        // recompute t exactly as phase 1, then scale
        float t0 = xl.x * invw * r4.x;
        float t1 = xl.y * invw * r4.y;
        float t2 = xl.z * invw * r4.z;
        float t3 = xl.w * invw * r4.w;
        float4 xn, bn;
        xn.x = t0 * invm; xn.y = t1 * invm;
        xn.z = t2 * invm; xn.w = t3 * invm;
        bn.x = (xn.x * xn.x * xn.x >= 0.5f) ? 1.0f : 0.0f;
        bn.y = (xn.y * xn.y * xn.y >= 0.5f) ? 1.0f : 0.0f;
        bn.z = (xn.z * xn.z * xn.z >= 0.5f) ? 1.0f : 0.0f;
        bn.w = (xn.w * xn.w * xn.w >= 0.5f) ? 1.0f : 0.0f;
        out_xn[f4]  = xn;
        out_bin[f4] = bn;
    }
}

// ---------------------------------------------------------------------------
extern "C" void kernel_launch(void* const* d_in, const int* in_sizes, int n_in,
                              void* d_out, int out_size) {
    const float* x  = (const float*)d_in[0];
    const float* Wl = (const float*)d_in[1];
    float* out = (float*)d_out;

    k_support<<<64 + SPIX_ / 256, 256>>>(Wl, x);    // 320 blocks: prep + chansum
    k_box<<<SPIX_ / 256, 256>>>();                  // 256 blocks
    k_fused<<<NPLANES_, FNT_>>>(x, out);            // 256 blocks x 1024
}

// round 12
// speedup vs baseline: 6.2050x; 1.1191x over previous
#include <cuda_runtime.h>
#include <math_constants.h>
#include <cstdint>

// Problem constants
#define B_      4
#define C_      64
#define H_      128
#define W_      128
#define LOC_    2
#define K_      5
#define KK_     25
#define CKK_    1600
#define NCHUNK_ 50                   // CKK_ / 32
#define PIX_    (H_ * W_)            // 16384
#define PIX4_   (PIX_ / 4)           // 4096
#define PLANE_  (B_ * C_ * PIX_)     // 4,194,304
#define SPIX_   (B_ * PIX_)          // 65536
#define NPLANES_ (B_ * C_)           // 256
#define FNT_    1024                 // fused threads per CTA
#define FPT_    4                    // float4 chunks per thread

// Scratch (allocation-free)
__device__ float    g_s[SPIX_];          // channel sum
__device__ float    g_rdenom[SPIX_];     // 1 / max(5x5 box sum, 5)
__device__ int      g_nnz[C_];
__device__ float    g_invw[C_];          // 1 / (1e-10 + row sum)
__device__ int      g_off[C_ * CKK_];    // c*PIX + dj*W + dk
__device__ int      g_dj[C_ * CKK_];
__device__ int      g_dk[C_ * CKK_];
__device__ float    g_w[C_ * CKK_];

// ---------------------------------------------------------------------------
// K1 (support): heterogeneous.
//   blocks 0..63   : sparsify W row o=blockIdx.x (warp 0 only).
//                    Loads are PRE-BATCHED into registers (50 independent
//                    LDGs in flight -> one latency exposure), then the
//                    ballot/compaction loop runs on registers only.
//   blocks 64..319 : channel sum, 256 px per block (scalar, coalesced)
// ---------------------------------------------------------------------------
__global__ void __launch_bounds__(256) k_support(const float* __restrict__ Wl,
                                                 const float* __restrict__ x) {
    const int tid = threadIdx.x;
    if (blockIdx.x < 64) {
        if (tid >= 32) return;
        const int o = blockIdx.x;
        const int lane = tid;
        const float* row = Wl + (size_t)o * CKK_;

        // Phase A: batched preload (independent LDGs, one latency exposure)
        float v[NCHUNK_];
#pragma unroll
        for (int i = 0; i < NCHUNK_; ++i)
            v[i] = __ldg(row + i * 32 + lane);

        // Phase B: ballot compaction on registers (ALU only)
        int cnt = 0;
        float s = 0.0f;
#pragma unroll
        for (int i = 0; i < NCHUNK_; ++i) {
            s += v[i];
            unsigned m = __ballot_sync(0xFFFFFFFFu, v[i] != 0.0f);
            if (v[i] != 0.0f) {
                int pos = cnt + __popc(m & ((1u << lane) - 1u));
                int k  = i * 32 + lane;
                int c  = k / KK_;
                int r  = k - c * KK_;
                int j  = r / K_;
                int kk = r - j * K_;
                int dj = j - LOC_, dk = kk - LOC_;
                g_off[o * CKK_ + pos] = c * PIX_ + dj * W_ + dk;
                g_dj [o * CKK_ + pos] = dj;
                g_dk [o * CKK_ + pos] = dk;
                g_w  [o * CKK_ + pos] = v[i];
            }
            cnt += __popc(m);
        }
#pragma unroll
        for (int off = 16; off > 0; off >>= 1)
            s += __shfl_xor_sync(0xFFFFFFFFu, s, off);
        if (lane == 0) {
            g_nnz[o] = cnt;
            g_invw[o] = 1.0f / (1e-10f + s);
        }
    } else {
        const int idx = (blockIdx.x - 64) * 256 + tid;   // 0..SPIX_-1
        const int b = idx >> 14;
        const int p = idx & (PIX_ - 1);
        const float* base = x + (size_t)b * C_ * PIX_ + p;
        float s = 0.0f;
#pragma unroll 16
        for (int c = 0; c < C_; ++c) s += base[(size_t)c * PIX_];
        g_s[idx] = s;
    }
}

// ---------------------------------------------------------------------------
// K2: 5x5 zero-padded box sum of s, rdenom = 1/max(acc, 5)
// ---------------------------------------------------------------------------
__global__ void __launch_bounds__(256) k_box(void) {
    int idx = blockIdx.x * blockDim.x + threadIdx.x;
    int b = idx >> 14;
    int p = idx & (PIX_ - 1);
    int h = p >> 7;
    int w = p & (W_ - 1);
    const float* sp = g_s + b * PIX_;
    float acc = 0.0f;
#pragma unroll
    for (int dj = -LOC_; dj <= LOC_; ++dj) {
        int hs = h + dj;
        if ((unsigned)hs >= H_) continue;
#pragma unroll
        for (int dk = -LOC_; dk <= LOC_; ++dk) {
            int ws = w + dk;
            if ((unsigned)ws >= W_) continue;
            acc += sp[hs * W_ + ws];
        }
    }
    g_rdenom[idx] = 1.0f / fmaxf(acc, (float)K_);
}

// ---------------------------------------------------------------------------
// K3 (fused): one CTA per (b,o) plane, 1024 threads, 2 CTAs/SM.
//   Phase 1 (per 4-px chunk): gather xl, write it, fold t into running max.
//   Block max barrier.
//   Phase 2: reload xl (L2-hot) + rdenom, recompute t identically, write
//   xn and bin.
// ---------------------------------------------------------------------------
__global__ void __launch_bounds__(FNT_, 2) k_fused(const float* __restrict__ x,
                                                   float* __restrict__ out) {
    __shared__ float s_red[FNT_ / 32];
    __shared__ float s_max;

    const int bo  = blockIdx.x;          // plane 0..255
    const int b   = bo >> 6;
    const int o   = bo & (C_ - 1);
    const int tid = threadIdx.x;

    const int   nnz  = g_nnz[o];
    const float invw = g_invw[o];
    const float* xb = x + (size_t)b * C_ * PIX_;
    const int lbase = o * CKK_;

    float4* out_xl = (float4*)(out + (size_t)bo * PIX_);
    const float4* rdn = (const float4*)(g_rdenom + b * PIX_);

    float lmax = -CUDART_INF_F;

#pragma unroll
    for (int i = 0; i < FPT_; ++i) {
        const int f4 = tid + i * FNT_;
        const int p0 = f4 * 4;
        const int h  = p0 >> 7;
        const int w0 = p0 & (W_ - 1);

        float a0 = 0.f, a1 = 0.f, a2 = 0.f, a3 = 0.f;
        for (int e = 0; e < nnz; ++e) {
            const int   off = __ldg(g_off + lbase + e);
            const int   dj  = __ldg(g_dj  + lbase + e);
            const int   dk  = __ldg(g_dk  + lbase + e);
            const float wv  = __ldg(g_w   + lbase + e);
            const int hs = h + dj;
            if ((unsigned)hs >= H_) continue;
            const float* src = xb + off + p0;
            if (dk == 0) {
                float4 v = *(const float4*)src;          // aligned
                a0 += wv * v.x; a1 += wv * v.y;
                a2 += wv * v.z; a3 += wv * v.w;
            } else {
                if ((unsigned)(w0 + 0 + dk) < W_) a0 += wv * src[0];
                if ((unsigned)(w0 + 1 + dk) < W_) a1 += wv * src[1];
                if ((unsigned)(w0 + 2 + dk) < W_) a2 += wv * src[2];
                if ((unsigned)(w0 + 3 + dk) < W_) a3 += wv * src[3];
            }
        }

        out_xl[f4] = make_float4(a0, a1, a2, a3);
        float4 r4 = rdn[f4];
        float t0 = a0 * invw * r4.x;
        float t1 = a1 * invw * r4.y;
        float t2 = a2 * invw * r4.z;
        float t3 = a3 * invw * r4.w;
        lmax = fmaxf(lmax, fmaxf(fmaxf(t0, t1), fmaxf(t2, t3)));
    }

    // block max reduction
#pragma unroll
    for (int off = 16; off > 0; off >>= 1)
        lmax = fmaxf(lmax, __shfl_xor_sync(0xFFFFFFFFu, lmax, off));
    if ((tid & 31) == 0) s_red[tid >> 5] = lmax;
    __syncthreads();
    if (tid < 32) {
        float v = s_red[tid];
#pragma unroll
        for (int off = 16; off > 0; off >>= 1)
            v = fmaxf(v, __shfl_xor_sync(0xFFFFFFFFu, v, off));
        if (tid == 0) s_max = v;
    }
    __syncthreads();

    const float invm = 1.0f / (1e-10f + s_max);
    float4* out_xn  = (float4*)(out + (size_t)PLANE_     + (size_t)bo * PIX_);
    float4* out_bin = (float4*)(out + (size_t)2 * PLANE_ + (size_t)bo * PIX_);

#pragma unroll
    for (int i = 0; i < FPT_; ++i) {
        const int f4 = tid + i * FNT_;
        float4 xl = out_xl[f4];                 // L2-hot reload
        float4 r4 = rdn[f4];
        float t0 = xl.x * invw * r4.x;
        float t1 = xl.y * invw * r4.y;
        float t2 = xl.z * invw * r4.z;
        float t3 = xl.w * invw * r4.w;
        float4 xn, bn;
        xn.x = t0 * invm; xn.y = t1 * invm;
        xn.z = t2 * invm; xn.w = t3 * invm;
        bn.x = (xn.x * xn.x * xn.x >= 0.5f) ? 1.0f : 0.0f;
        bn.y = (xn.y * xn.y * xn.y >= 0.5f) ? 1.0f : 0.0f;
        bn.z = (xn.z * xn.z * xn.z >= 0.5f) ? 1.0f : 0.0f;
        bn.w = (xn.w * xn.w * xn.w >= 0.5f) ? 1.0f : 0.0f;
        out_xn[f4]  = xn;
        out_bin[f4] = bn;
    }
}

// ---------------------------------------------------------------------------
extern "C" void kernel_launch(void* const* d_in, const int* in_sizes, int n_in,
                              void* d_out, int out_size) {
    const float* x  = (const float*)d_in[0];
    const float* Wl = (const float*)d_in[1];
    float* out = (float*)d_out;

    k_support<<<64 + SPIX_ / 256, 256>>>(Wl, x);    // 320 blocks: prep + chansum
    k_box<<<SPIX_ / 256, 256>>>();                  // 256 blocks
    k_fused<<<NPLANES_, FNT_>>>(x, out);            // 256 blocks x 1024
}

// round 13
// speedup vs baseline: 6.2222x; 1.0028x over previous
#include <cuda_runtime.h>
#include <math_constants.h>
#include <cstdint>

// Problem constants
#define B_      4
#define C_      64
#define H_      128
#define W_      128
#define LOC_    2
#define K_      5
#define KK_     25
#define CKK_    1600
#define PIX_    (H_ * W_)            // 16384
#define PIX4_   (PIX_ / 4)           // 4096
#define PLANE_  (B_ * C_ * PIX_)     // 4,194,304
#define SPIX_   (B_ * PIX_)          // 65536
#define NPLANES_ (B_ * C_)           // 256
#define FNT_    1024                 // fused threads per CTA
#define FPT_    4                    // float4 chunks per thread

// k_support layout: blocks 0..63 prep, blocks 64..575 chansum
#define PREPB_   64
#define CSB_     512                 // chansum blocks (SPIX_/128)
#define CGRP_    8                   // channel groups per block
#define CPERG_   (C_ / CGRP_)        // 8 channels per group
#define F4PB_    32                  // float4 pixels per chansum block (128 px)

// Scratch (allocation-free)
__device__ float    g_s[SPIX_];          // channel sum
__device__ float    g_rdenom[SPIX_];     // 1 / max(5x5 box sum, 5)
__device__ int      g_nnz[C_];
__device__ float    g_invw[C_];          // 1 / (1e-10 + row sum)
__device__ int      g_off[C_ * CKK_];    // c*PIX + dj*W + dk
__device__ int      g_dj[C_ * CKK_];
__device__ int      g_dk[C_ * CKK_];
__device__ float    g_w[C_ * CKK_];

// ---------------------------------------------------------------------------
// K1 (support): heterogeneous, 576 blocks x 256 threads.
//   blocks 0..63    : sparsify W row o=blockIdx.x. 256 threads coalesce-load
//                     the row into smem (one latency exposure); warp 0 then
//                     runs ballot compaction from smem (no global latency).
//   blocks 64..575  : channel sum. Each block owns 32 float4 pixels; threads
//                     split 8-ways over channels (8 independent float4 LDGs
//                     each), combined through one smem stage (fixed order).
// ---------------------------------------------------------------------------
__global__ void __launch_bounds__(256) k_support(const float* __restrict__ Wl,
                                                 const float* __restrict__ x) {
    const int tid = threadIdx.x;
    if (blockIdx.x < PREPB_) {
        __shared__ float s_row[CKK_];
        const int o = blockIdx.x;
        const float* row = Wl + (size_t)o * CKK_;
        // coalesced stage: 1600 floats, 256 threads -> 7 loads each (indep)
        for (int i = tid; i < CKK_; i += 256)
            s_row[i] = __ldg(row + i);
        __syncthreads();

        if (tid >= 32) return;
        const int lane = tid;
        int cnt = 0;
        float s = 0.0f;
#pragma unroll
        for (int i = 0; i < CKK_ / 32; ++i) {
            float v = s_row[i * 32 + lane];
            s += v;
            unsigned m = __ballot_sync(0xFFFFFFFFu, v != 0.0f);
            if (v != 0.0f) {
                int pos = cnt + __popc(m & ((1u << lane) - 1u));
                int k  = i * 32 + lane;
                int c  = k / KK_;
                int r  = k - c * KK_;
                int j  = r / K_;
                int kk = r - j * K_;
                int dj = j - LOC_, dk = kk - LOC_;
                g_off[o * CKK_ + pos] = c * PIX_ + dj * W_ + dk;
                g_dj [o * CKK_ + pos] = dj;
                g_dk [o * CKK_ + pos] = dk;
                g_w  [o * CKK_ + pos] = v;
            }
            cnt += __popc(m);
        }
#pragma unroll
        for (int off = 16; off > 0; off >>= 1)
            s += __shfl_xor_sync(0xFFFFFFFFu, s, off);
        if (lane == 0) {
            g_nnz[o] = cnt;
            g_invw[o] = 1.0f / (1e-10f + s);
        }
    } else {
        __shared__ float4 s_part[CGRP_][F4PB_];
        const int blk = blockIdx.x - PREPB_;         // 0..511
        const int b   = blk >> 7;                    // 128 blocks per batch
        const int f4base = (blk & 127) * F4PB_;      // float4 offset in plane
        const int lane = tid & (F4PB_ - 1);          // 0..31: pixel f4
        const int grp  = tid >> 5;                   // 0..7 : channel group

        const float4* base = (const float4*)x + (size_t)b * C_ * PIX4_
                             + f4base + lane;
        float4 s = make_float4(0.f, 0.f, 0.f, 0.f);
#pragma unroll
        for (int c = 0; c < CPERG_; ++c) {
            float4 v = __ldg(base + (size_t)(grp * CPERG_ + c) * PIX4_);
            s.x += v.x; s.y += v.y; s.z += v.z; s.w += v.w;
        }
        s_part[grp][lane] = s;
        __syncthreads();
        if (grp == 0) {
            float4 acc = s_part[0][lane];
#pragma unroll
            for (int g = 1; g < CGRP_; ++g) {
                float4 v = s_part[g][lane];
                acc.x += v.x; acc.y += v.y; acc.z += v.z; acc.w += v.w;
            }
            ((float4*)g_s)[(size_t)b * PIX4_ + f4base + lane] = acc;
        }
    }
}

// ---------------------------------------------------------------------------
// K2: 5x5 zero-padded box sum of s, rdenom = 1/max(acc, 5)
// ---------------------------------------------------------------------------
__global__ void __launch_bounds__(256) k_box(void) {
    int idx = blockIdx.x * blockDim.x + threadIdx.x;
    int b = idx >> 14;
    int p = idx & (PIX_ - 1);
    int h = p >> 7;
    int w = p & (W_ - 1);
    const float* sp = g_s + b * PIX_;
    float acc = 0.0f;
#pragma unroll
    for (int dj = -LOC_; dj <= LOC_; ++dj) {
        int hs = h + dj;
        if ((unsigned)hs >= H_) continue;
#pragma unroll
        for (int dk = -LOC_; dk <= LOC_; ++dk) {
            int ws = w + dk;
            if ((unsigned)ws >= W_) continue;
            acc += sp[hs * W_ + ws];
        }
    }
    g_rdenom[idx] = 1.0f / fmaxf(acc, (float)K_);
}

// ---------------------------------------------------------------------------
// K3 (fused): one CTA per (b,o) plane, 1024 threads, 2 CTAs/SM.
//   Phase 1 (per 4-px chunk): gather xl, write it, fold t into running max.
//   Block max barrier.
//   Phase 2: reload xl (L2-hot) + rdenom, recompute t identically, write
//   xn and bin.
// ---------------------------------------------------------------------------
__global__ void __launch_bounds__(FNT_, 2) k_fused(const float* __restrict__ x,
                                                   float* __restrict__ out) {
    __shared__ float s_red[FNT_ / 32];
    __shared__ float s_max;

    const int bo  = blockIdx.x;          // plane 0..255
    const int b   = bo >> 6;
    const int o   = bo & (C_ - 1);
    const int tid = threadIdx.x;

    const int   nnz  = g_nnz[o];
    const float invw = g_invw[o];
    const float* xb = x + (size_t)b * C_ * PIX_;
    const int lbase = o * CKK_;

    float4* out_xl = (float4*)(out + (size_t)bo * PIX_);
    const float4* rdn = (const float4*)(g_rdenom + b * PIX_);

    float lmax = -CUDART_INF_F;

#pragma unroll
    for (int i = 0; i < FPT_; ++i) {
        const int f4 = tid + i * FNT_;
        const int p0 = f4 * 4;
        const int h  = p0 >> 7;
        const int w0 = p0 & (W_ - 1);

        float a0 = 0.f, a1 = 0.f, a2 = 0.f, a3 = 0.f;
        for (int e = 0; e < nnz; ++e) {
            const int   off = __ldg(g_off + lbase + e);
            const int   dj  = __ldg(g_dj  + lbase + e);
            const int   dk  = __ldg(g_dk  + lbase + e);
            const float wv  = __ldg(g_w   + lbase + e);
            const int hs = h + dj;
            if ((unsigned)hs >= H_) continue;
            const float* src = xb + off + p0;
            if (dk == 0) {
                float4 v = *(const float4*)src;          // aligned
                a0 += wv * v.x; a1 += wv * v.y;
                a2 += wv * v.z; a3 += wv * v.w;
            } else {
                if ((unsigned)(w0 + 0 + dk) < W_) a0 += wv * src[0];
                if ((unsigned)(w0 + 1 + dk) < W_) a1 += wv * src[1];
                if ((unsigned)(w0 + 2 + dk) < W_) a2 += wv * src[2];
                if ((unsigned)(w0 + 3 + dk) < W_) a3 += wv * src[3];
            }
        }

        out_xl[f4] = make_float4(a0, a1, a2, a3);
        float4 r4 = rdn[f4];
        float t0 = a0 * invw * r4.x;
        float t1 = a1 * invw * r4.y;
        float t2 = a2 * invw * r4.z;
        float t3 = a3 * invw * r4.w;
        lmax = fmaxf(lmax, fmaxf(fmaxf(t0, t1), fmaxf(t2, t3)));
    }

    // block max reduction
#pragma unroll
    for (int off = 16; off > 0; off >>= 1)
        lmax = fmaxf(lmax, __shfl_xor_sync(0xFFFFFFFFu, lmax, off));
    if ((tid & 31) == 0) s_red[tid >> 5] = lmax;
    __syncthreads();
    if (tid < 32) {
        float v = s_red[tid];
#pragma unroll
        for (int off = 16; off > 0; off >>= 1)
            v = fmaxf(v, __shfl_xor_sync(0xFFFFFFFFu, v, off));
        if (tid == 0) s_max = v;
    }
    __syncthreads();

    const float invm = 1.0f / (1e-10f + s_max);
    float4* out_xn  = (float4*)(out + (size_t)PLANE_     + (size_t)bo * PIX_);
    float4* out_bin = (float4*)(out + (size_t)2 * PLANE_ + (size_t)bo * PIX_);

#pragma unroll
    for (int i = 0; i < FPT_; ++i) {
        const int f4 = tid + i * FNT_;
        float4 xl = out_xl[f4];                 // L2-hot reload
        float4 r4 = rdn[f4];
        float t0 = xl.x * invw * r4.x;
        float t1 = xl.y * invw * r4.y;
        float t2 = xl.z * invw * r4.z;
        float t3 = xl.w * invw * r4.w;
        float4 xn, bn;
        xn.x = t0 * invm; xn.y = t1 * invm;
        xn.z = t2 * invm; xn.w = t3 * invm;
        bn.x = (xn.x * xn.x * xn.x >= 0.5f) ? 1.0f : 0.0f;
        bn.y = (xn.y * xn.y * xn.y >= 0.5f) ? 1.0f : 0.0f;
        bn.z = (xn.z * xn.z * xn.z >= 0.5f) ? 1.0f : 0.0f;
        bn.w = (xn.w * xn.w * xn.w >= 0.5f) ? 1.0f : 0.0f;
        out_xn[f4]  = xn;
        out_bin[f4] = bn;
    }
}

// ---------------------------------------------------------------------------
extern "C" void kernel_launch(void* const* d_in, const int* in_sizes, int n_in,
                              void* d_out, int out_size) {
    const float* x  = (const float*)d_in[0];
    const float* Wl = (const float*)d_in[1];
    float* out = (float*)d_out;

    k_support<<<PREPB_ + CSB_, 256>>>(Wl, x);       // 576 blocks
    k_box<<<SPIX_ / 256, 256>>>();                  // 256 blocks
    k_fused<<<NPLANES_, FNT_>>>(x, out);            // 256 blocks x 1024
}

// round 15
// speedup vs baseline: 6.8397x; 1.0992x over previous
#include <cuda_runtime.h>
#include <math_constants.h>
#include <cstdint>

// Problem constants
#define B_      4
#define C_      64
#define H_      128
#define W_      128
#define LOC_    2
#define K_      5
#define KK_     25
#define CKK_    1600
#define NCHUNK_ 50                   // CKK_/32
#define PIX_    (H_ * W_)            // 16384
#define PIX4_   (PIX_ / 4)           // 4096
#define PLANE_  (B_ * C_ * PIX_)     // 4,194,304
#define SPIX_   (B_ * PIX_)          // 65536
#define NPLANES_ (B_ * C_)           // 256
#define FNT_    1024                 // fused threads per CTA
#define FPT_    4                    // float4 chunks per thread

// K1 layout: blocks 0..63 = prep; blocks 64..191 = chansum+box stripes
#define PREPB_   64
#define ROWSPB_  4                   // owned rows per stripe block
#define EXTR_    (ROWSPB_ + 2 * LOC_)   // 8 extended rows
#define CSBB_    (B_ * H_ / ROWSPB_)    // 128 stripe blocks

// Scratch (allocation-free)
__device__ float    g_rdenom[SPIX_];     // 1 / max(5x5 box sum of chansum, 5)
__device__ int      g_nnz[C_];
__device__ float    g_invw[C_];          // 1 / (1e-10 + row sum)
__device__ int      g_off[C_ * CKK_];    // c*PIX + dj*W + dk
__device__ int      g_dj[C_ * CKK_];
__device__ int      g_dk[C_ * CKK_];
__device__ float    g_w[C_ * CKK_];

// ---------------------------------------------------------------------------
// K1: heterogeneous, 192 blocks x 256 threads.
//   blocks 0..63   : sparsify W row o (register-preload + ballot compaction)
//   blocks 64..191 : fused chansum + 5x5 box for a 4-row stripe of one batch.
//                    Channel sums for the 8 extended rows go to smem (zero
//                    outside image); then box-sum + clamp + reciprocal.
// ---------------------------------------------------------------------------
__global__ void __launch_bounds__(256) k_support(const float* __restrict__ Wl,
                                                 const float* __restrict__ x) {
    const int tid = threadIdx.x;
    if (blockIdx.x < PREPB_) {
        if (tid >= 32) return;
        const int o = blockIdx.x;
        const int lane = tid;
        const float* row = Wl + (size_t)o * CKK_;

        // batched preload: 50 independent LDGs, one latency exposure
        float v[NCHUNK_];
#pragma unroll
        for (int i = 0; i < NCHUNK_; ++i)
            v[i] = __ldg(row + i * 32 + lane);

        int cnt = 0;
        float s = 0.0f;
#pragma unroll
        for (int i = 0; i < NCHUNK_; ++i) {
            s += v[i];
            unsigned m = __ballot_sync(0xFFFFFFFFu, v[i] != 0.0f);
            if (v[i] != 0.0f) {
                int pos = cnt + __popc(m & ((1u << lane) - 1u));
                int k  = i * 32 + lane;
                int c  = k / KK_;
                int r  = k - c * KK_;
                int j  = r / K_;
                int kk = r - j * K_;
                int dj = j - LOC_, dk = kk - LOC_;
                g_off[o * CKK_ + pos] = c * PIX_ + dj * W_ + dk;
                g_dj [o * CKK_ + pos] = dj;
                g_dk [o * CKK_ + pos] = dk;
                g_w  [o * CKK_ + pos] = v[i];
            }
            cnt += __popc(m);
        }
#pragma unroll
        for (int off = 16; off > 0; off >>= 1)
            s += __shfl_xor_sync(0xFFFFFFFFu, s, off);
        if (lane == 0) {
            g_nnz[o] = cnt;
            g_invw[o] = 1.0f / (1e-10f + s);
        }
    } else {
        __shared__ float s_sum[EXTR_][W_];
        const int blk = blockIdx.x - PREPB_;          // 0..127
        const int b   = blk >> 5;                     // 32 stripes per batch
        const int r0  = (blk & 31) * ROWSPB_;         // first owned row

        // chansum for 8 extended rows x 128 cols; one float4-pixel per thread
        {
            const int j  = tid >> 5;                  // extended row 0..7
            const int w4 = tid & 31;                  // float4 col 0..31
            const int er = r0 - LOC_ + j;
            float4 s = make_float4(0.f, 0.f, 0.f, 0.f);
            if ((unsigned)er < H_) {
                const float4* base = (const float4*)x + (size_t)b * C_ * PIX4_
                                     + er * (W_ / 4) + w4;
#pragma unroll 16
                for (int c = 0; c < C_; ++c) {
                    float4 v = __ldg(base + (size_t)c * PIX4_);
                    s.x += v.x; s.y += v.y; s.z += v.z; s.w += v.w;
                }
            }
            s_sum[j][w4 * 4 + 0] = s.x;
            s_sum[j][w4 * 4 + 1] = s.y;
            s_sum[j][w4 * 4 + 2] = s.z;
            s_sum[j][w4 * 4 + 3] = s.w;
        }
        __syncthreads();

        // 5x5 box over smem for the 4 owned rows (512 px, 2 per thread)
        for (int i = tid; i < ROWSPB_ * W_; i += 256) {
            const int rr = i >> 7;                    // owned row 0..3
            const int w  = i & (W_ - 1);
            float acc = 0.0f;
#pragma unroll
            for (int dj = 0; dj < K_; ++dj) {
#pragma unroll
                for (int dk = -LOC_; dk <= LOC_; ++dk) {
                    const int ws = w + dk;
                    if ((unsigned)ws < W_) acc += s_sum[rr + dj][ws];
                }
            }
            g_rdenom[b * PIX_ + (r0 + rr) * W_ + w] = 1.0f / fmaxf(acc, (float)K_);
        }
    }
}

// ---------------------------------------------------------------------------
// K2 (fused): one CTA per (b,o) plane, 1024 threads, 2 CTAs/SM.
//   Phase 1 (per 4-px chunk): gather xl, write it, fold t into running max.
//   Block max barrier.
//   Phase 2: reload xl (L2-hot) + rdenom, recompute t identically, write
//   xn and bin.
// ---------------------------------------------------------------------------
__global__ void __launch_bounds__(FNT_, 2) k_fused(const float* __restrict__ x,
                                                   float* __restrict__ out) {
    __shared__ float s_red[FNT_ / 32];
    __shared__ float s_max;

    const int bo  = blockIdx.x;          // plane 0..255
    const int b   = bo >> 6;
    const int o   = bo & (C_ - 1);
    const int tid = threadIdx.x;

    const int   nnz  = g_nnz[o];
    const float invw = g_invw[o];
    const float* xb = x + (size_t)b * C_ * PIX_;
    const int lbase = o * CKK_;

    float4* out_xl = (float4*)(out + (size_t)bo * PIX_);
    const float4* rdn = (const float4*)(g_rdenom + b * PIX_);

    float lmax = -CUDART_INF_F;

#pragma unroll
    for (int i = 0; i < FPT_; ++i) {
        const int f4 = tid + i * FNT_;
        const int p0 = f4 * 4;
        const int h  = p0 >> 7;
        const int w0 = p0 & (W_ - 1);

        float a0 = 0.f, a1 = 0.f, a2 = 0.f, a3 = 0.f;
        for (int e = 0; e < nnz; ++e) {
            const int   off = __ldg(g_off + lbase + e);
            const int   dj  = __ldg(g_dj  + lbase + e);
            const int   dk  = __ldg(g_dk  + lbase + e);
            const float wv  = __ldg(g_w   + lbase + e);
            const int hs = h + dj;
            if ((unsigned)hs >= H_) continue;
            const float* src = xb + off + p0;
            if (dk == 0) {
                float4 v = *(const float4*)src;          // aligned
                a0 += wv * v.x; a1 += wv * v.y;
                a2 += wv * v.z; a3 += wv * v.w;
            } else {
                if ((unsigned)(w0 + 0 + dk) < W_) a0 += wv * src[0];
                if ((unsigned)(w0 + 1 + dk) < W_) a1 += wv * src[1];
                if ((unsigned)(w0 + 2 + dk) < W_) a2 += wv * src[2];
                if ((unsigned)(w0 + 3 + dk) < W_) a3 += wv * src[3];
            }
        }

        out_xl[f4] = make_float4(a0, a1, a2, a3);
        float4 r4 = rdn[f4];
        float t0 = a0 * invw * r4.x;
        float t1 = a1 * invw * r4.y;
        float t2 = a2 * invw * r4.z;
        float t3 = a3 * invw * r4.w;
        lmax = fmaxf(lmax, fmaxf(fmaxf(t0, t1), fmaxf(t2, t3)));
    }

    // block max reduction
#pragma unroll
    for (int off = 16; off > 0; off >>= 1)
        lmax = fmaxf(lmax, __shfl_xor_sync(0xFFFFFFFFu, lmax, off));
    if ((tid & 31) == 0) s_red[tid >> 5] = lmax;
    __syncthreads();
    if (tid < 32) {
        float v = s_red[tid];
#pragma unroll
        for (int off = 16; off > 0; off >>= 1)
            v = fmaxf(v, __shfl_xor_sync(0xFFFFFFFFu, v, off));
        if (tid == 0) s_max = v;
    }
    __syncthreads();

    const float invm = 1.0f / (1e-10f + s_max);
    float4* out_xn  = (float4*)(out + (size_t)PLANE_     + (size_t)bo * PIX_);
    float4* out_bin = (float4*)(out + (size_t)2 * PLANE_ + (size_t)bo * PIX_);

#pragma unroll
    for (int i = 0; i < FPT_; ++i) {
        const int f4 = tid + i * FNT_;
        float4 xl = out_xl[f4];                 // L2-hot reload
        float4 r4 = rdn[f4];
        float t0 = xl.x * invw * r4.x;
        float t1 = xl.y * invw * r4.y;
        float t2 = xl.z * invw * r4.z;
        float t3 = xl.w * invw * r4.w;
        float4 xn, bn;
        xn.x = t0 * invm; xn.y = t1 * invm;
        xn.z = t2 * invm; xn.w = t3 * invm;
        bn.x = (xn.x * xn.x * xn.x >= 0.5f) ? 1.0f : 0.0f;
        bn.y = (xn.y * xn.y * xn.y >= 0.5f) ? 1.0f : 0.0f;
        bn.z = (xn.z * xn.z * xn.z >= 0.5f) ? 1.0f : 0.0f;
        bn.w = (xn.w * xn.w * xn.w >= 0.5f) ? 1.0f : 0.0f;
        out_xn[f4]  = xn;
        out_bin[f4] = bn;
    }
}

// ---------------------------------------------------------------------------
extern "C" void kernel_launch(void* const* d_in, const int* in_sizes, int n_in,
                              void* d_out, int out_size) {
    const float* x  = (const float*)d_in[0];
    const float* Wl = (const float*)d_in[1];
    float* out = (float*)d_out;

    k_support<<<PREPB_ + CSBB_, 256>>>(Wl, x);      // 192 blocks: prep + cs+box
    k_fused<<<NPLANES_, FNT_>>>(x, out);            // 256 blocks x 1024
}